// round 12
// baseline (speedup 1.0000x reference)
#include <cuda_runtime.h>
#include <cuda_bf16.h>
#include <cstddef>

// Problem constants (fixed shapes from reference)
#define B_   64
#define T_   4096
#define F_   64
#define H_   256
#define EPS_ 1e-8f
#define ALPHA_ 0.5f

// Block owns 256 t. Scan split into 4 sub-chunks of 64 t (one per warp-pair),
// each with a 48-step warm-up (0.5^48 ~ 3.6e-15: exact to fp32).
// 112 total steps = 16 macro-iters * 7 steps; 16 iters * 2 rows * 8 warps = 256 rows.
#define CHUNK_  256
#define NCHUNK_ (T_ / CHUNK_)       // 16
#define SUB_    64
#define WARM_   48
#define NMACRO_ 16
#define STEPS_  7                   // (WARM_+SUB_)/NMACRO_

#define GRID_   (B_ * NCHUNK_)      // 1024
#define TPB_    256

// Scratch (device globals: no allocation allowed)
__device__ float g_penPart[GRID_];
__device__ float g_msePart[GRID_];
__device__ int   g_ticket;          // zero-initialized; reset by last block

__device__ __forceinline__ void ewa_step(float& m, float& v, float& c,
                                         float xt, float xl)
{
    m = fmaf(0.5f, xt - m, m);          // m = 0.5 m + 0.5 xt
    float r = xt - m;
    v = fmaf(0.5f, fmaf(r, r, -v), v);  // v = 0.5 v + 0.5 r^2
    float q = xl - m;
    c = fmaf(0.5f, fmaf(r, q, -c), c);  // c = 0.5 c + 0.5 r q
}

// ---------------------------------------------------------------------------
// Fully interleaved fused kernel (no mid-kernel phase barrier).
// Per warp, per macro-iteration (16 of them):
//   1) issue 4 independent float4 fg loads (one row-pair)  [fills DRAM pipe]
//   2) run 7 EWA scan steps in the load shadow; steps in the main region
//      butterfly-reduce irr over the warp -> irrP smem
//   3) consume the loads: rowsum -> Gs smem
// Epilogue (single barrier): pen = sum_t (irrP0[t]+irrP1[t]) * Gs[t].
// ---------------------------------------------------------------------------
__global__ void __launch_bounds__(TPB_) kFused(
    const float* __restrict__ fg,
    const float* __restrict__ seq,
    const float* __restrict__ inp,
    const float* __restrict__ tgt,
    float* __restrict__ out)
{
    __shared__ float  Gs[CHUNK_];
    __shared__ float  irrP[2][CHUNK_];
    __shared__ float  redA[TPB_ / 32];
    __shared__ float  redM[TPB_ / 32];
    __shared__ int    s_ticket;
    __shared__ double dP[TPB_ / 32], dM[TPB_ / 32];

    const int tid  = threadIdx.x;
    const int wid  = tid >> 5;
    const int lane = tid & 31;
    const int b     = blockIdx.x >> 4;            // / NCHUNK_
    const int chunk = blockIdx.x & (NCHUNK_ - 1);
    const int t0    = chunk * CHUNK_;

    const float4* __restrict__ fg4 = (const float4*)fg;

    // ---- MSE: exactly one element per thread (B*T == GRID_*TPB_) ----
    float ms;
    {
        const int i = blockIdx.x * TPB_ + tid;
        float d = inp[i] - tgt[i];
        ms = d * d;
    }

    // ---- Scan setup: thread = (f, sub-chunk g) ----
    const int f   = tid & (F_ - 1);
    const int g   = tid >> 6;                     // 0..3
    const int ts  = t0 + g * SUB_;                // sub-chunk start
    const int tlo = (ts == 0) ? 1 : ts - WARM_;   // first valid warm step
    const int tsm = (ts == 0) ? 1 : ts;           // first main-region step
    const float* __restrict__ sp = seq + (size_t)b * T_ * F_ + f;

    float m = 0.0f, v = EPS_, c = 0.0f;
    float xl = sp[(size_t)(tlo - 1) * F_];
    int   t  = ts - WARM_;                        // may be < tlo (chunk0,g0)

    const size_t rowbase = (size_t)(b * T_ + t0) * (H_ / 4);
    const int    wsel    = wid & 1;               // irrP partial bank

    // ---- 16 macro-iterations: one row-pair load + 7 scan steps each ----
    #pragma unroll 1
    for (int i = 0; i < NMACRO_; ++i) {
        const int r = wid * 2 + i * 16;           // covers 0..255 over 16 iters
        const size_t b0 = rowbase + (size_t)r * (H_ / 4);
        float4 a0 = fg4[b0 + lane];
        float4 a1 = fg4[b0 + 32 + lane];
        float4 c0 = fg4[b0 + 64 + lane];
        float4 c1 = fg4[b0 + 96 + lane];

        #pragma unroll
        for (int j = 0; j < STEPS_; ++j) {
            if (t >= tsm) {                       // main region (warp-uniform)
                float xt = sp[(size_t)t * F_];
                ewa_step(m, v, c, xt, xl);
                xl = xt;
                float ac  = c * rsqrtf(fmaf(v, v, EPS_));
                float irr = 1.0f - fabsf(ac);
                #pragma unroll
                for (int o = 16; o; o >>= 1)
                    irr += __shfl_xor_sync(0xffffffffu, irr, o);
                if (lane == 0) irrP[wsel][t - t0] = irr;
            } else if (t >= tlo) {                // warm-up (warp-uniform)
                float xt = sp[(size_t)t * F_];
                ewa_step(m, v, c, xt, xl);
                xl = xt;
            }
            ++t;
        }

        float s0 = (a0.x + a0.y) + (a0.z + a0.w) + (a1.x + a1.y) + (a1.z + a1.w);
        float s1 = (c0.x + c0.y) + (c0.z + c0.w) + (c1.x + c1.y) + (c1.z + c1.w);
        #pragma unroll
        for (int o = 16; o; o >>= 1) {
            s0 += __shfl_xor_sync(0xffffffffu, s0, o);
            s1 += __shfl_xor_sync(0xffffffffu, s1, o);
        }
        if (lane == 0) { Gs[r] = s0; Gs[r + 1] = s1; }
    }

    __syncthreads();   // the ONLY mid-kernel barrier

    // ---- Epilogue: pen partial = sum_t irrSum[t] * G[t] (1 t per thread) ----
    float is = irrP[0][tid] + irrP[1][tid];
    if (chunk == 0 && tid == 0) is = (float)F_;   // t=0: ac=0 -> irr=1 per f
    float pen = is * Gs[tid];

    #pragma unroll
    for (int o = 16; o; o >>= 1) {
        ms  += __shfl_xor_sync(0xffffffffu, ms, o);
        pen += __shfl_xor_sync(0xffffffffu, pen, o);
    }
    if (lane == 0) { redM[wid] = ms; redA[wid] = pen; }
    __syncthreads();
    if (tid == 0) {
        float M = 0.0f, A = 0.0f;
        #pragma unroll
        for (int i = 0; i < TPB_ / 32; ++i) { M += redM[i]; A += redA[i]; }
        g_msePart[blockIdx.x] = M;
        g_penPart[blockIdx.x] = A;
        __threadfence();
        s_ticket = atomicAdd(&g_ticket, 1);
    }
    __syncthreads();

    // ---- Last block: deterministic double-precision finalize ----
    if (s_ticket == GRID_ - 1) {
        double pend = 0.0, msed = 0.0;
        for (int i = tid; i < GRID_; i += TPB_) {
            pend += (double)g_penPart[i];
            msed += (double)g_msePart[i];
        }
        #pragma unroll
        for (int o = 16; o; o >>= 1) {
            pend += __shfl_xor_sync(0xffffffffu, pend, o);
            msed += __shfl_xor_sync(0xffffffffu, msed, o);
        }
        if (lane == 0) { dP[wid] = pend; dM[wid] = msed; }
        __syncthreads();
        if (tid == 0) {
            double P = 0.0, M = 0.0;
            #pragma unroll
            for (int i = 0; i < TPB_ / 32; ++i) { P += dP[i]; M += dM[i]; }
            double penalty = P / ((double)B_ * T_ * F_ * H_);
            double msev    = M / ((double)B_ * T_);
            out[0] = (float)(msev + (double)ALPHA_ * penalty);
            g_ticket = 0;                 // reset for next graph replay
        }
    }
}

// ---------------------------------------------------------------------------
extern "C" void kernel_launch(void* const* d_in, const int* in_sizes, int n_in,
                              void* d_out, int out_size)
{
    const float* inp = (const float*)d_in[0];   // input    (B,T,1)
    const float* tgt = (const float*)d_in[1];   // target   (B,T,1)
    const float* seq = (const float*)d_in[2];   // sequence (B,T,F)
    const float* fg  = (const float*)d_in[3];   // forget_gates (B,T,H)
    float* out = (float*)d_out;

    kFused<<<GRID_, TPB_>>>(fg, seq, inp, tgt, out);
}

// round 13
// speedup vs baseline: 2.0235x; 2.0235x over previous
#include <cuda_runtime.h>
#include <cuda_bf16.h>
#include <cstddef>

// Problem constants (fixed shapes from reference)
#define B_   64
#define T_   4096
#define F_   64
#define H_   256
#define EPS_ 1e-8f
#define ALPHA_ 0.5f

// Block owns 256 t. Scan split into 4 sub-chunks of 64 t (one per warp-pair),
// each with a 40-step warm-up (0.5^40 ~ 1e-12: exact to fp32).
#define CHUNK_  256
#define NCHUNK_ (T_ / CHUNK_)       // 16
#define SUB_    64
#define WARM_   40

#define GRID_   (B_ * NCHUNK_)      // 1024
#define TPB_    256

// Scratch (device globals: no allocation allowed)
__device__ float g_penPart[GRID_];
__device__ float g_msePart[GRID_];
__device__ int   g_ticket;          // zero-initialized; reset by last block

__device__ __forceinline__ void ewa_step(float& m, float& v, float& c,
                                         float xt, float xl)
{
    m = fmaf(0.5f, xt - m, m);          // m = 0.5 m + 0.5 xt
    float r = xt - m;
    v = fmaf(0.5f, fmaf(r, r, -v), v);  // v = 0.5 v + 0.5 r^2
    float q = xl - m;
    c = fmaf(0.5f, fmaf(r, q, -c), c);  // c = 0.5 c + 0.5 r q
}

// ---------------------------------------------------------------------------
// Fused kernel, warp-level phase staggering, NO inter-phase barrier:
//   warps 0-3: rowsum(32 fg rows each -> Gs)  then  scan(own sub-chunk -> irrP)
//   warps 4-7: scan  then  rowsum
// The two phases touch disjoint smem (Gs vs irrP) and have no data dependency;
// a single __syncthreads() precedes the dot-product epilogue:
//   pen = sum_t (irrP[0][t] + irrP[1][t]) * Gs[t]
// ---------------------------------------------------------------------------
__global__ void __launch_bounds__(TPB_) kFused(
    const float* __restrict__ fg,
    const float* __restrict__ seq,
    const float* __restrict__ inp,
    const float* __restrict__ tgt,
    float* __restrict__ out)
{
    __shared__ float  Gs[CHUNK_];
    __shared__ float  irrP[2][CHUNK_];
    __shared__ float  redA[TPB_ / 32];
    __shared__ float  redM[TPB_ / 32];
    __shared__ int    s_ticket;
    __shared__ double dP[TPB_ / 32], dM[TPB_ / 32];

    const int tid  = threadIdx.x;
    const int wid  = tid >> 5;
    const int lane = tid & 31;
    const int b     = blockIdx.x >> 4;            // / NCHUNK_
    const int chunk = blockIdx.x & (NCHUNK_ - 1);
    const int t0    = chunk * CHUNK_;

    const float4* __restrict__ fg4 = (const float4*)fg;

    // ---- MSE: exactly one element per thread (B*T == GRID_*TPB_) ----
    float ms;
    {
        const int i = blockIdx.x * TPB_ + tid;
        float d = inp[i] - tgt[i];
        ms = d * d;
    }

    // ---- Phase work definitions ----
    auto do_rowsum = [&]() {
        const size_t rowbase = (size_t)(b * T_ + t0) * (H_ / 4);
        #pragma unroll 2
        for (int r = wid * 2; r < CHUNK_; r += 16) {
            size_t b0 = rowbase + (size_t)r * (H_ / 4);
            size_t b1 = b0 + (H_ / 4);
            float4 a0 = fg4[b0 + lane];
            float4 a1 = fg4[b0 + 32 + lane];
            float4 c0 = fg4[b1 + lane];
            float4 c1 = fg4[b1 + 32 + lane];
            float s0 = (a0.x + a0.y) + (a0.z + a0.w) + (a1.x + a1.y) + (a1.z + a1.w);
            float s1 = (c0.x + c0.y) + (c0.z + c0.w) + (c1.x + c1.y) + (c1.z + c1.w);
            #pragma unroll
            for (int o = 16; o; o >>= 1) {
                s0 += __shfl_xor_sync(0xffffffffu, s0, o);
                s1 += __shfl_xor_sync(0xffffffffu, s1, o);
            }
            if (lane == 0) { Gs[r] = s0; Gs[r + 1] = s1; }
        }
    };

    auto do_scan = [&]() {
        const int f  = tid & (F_ - 1);
        const int g  = tid >> 6;                  // sub-chunk 0..3
        const int ts = t0 + g * SUB_;             // sub-chunk start
        const int wsel = wid & 1;                 // irrP bank (f<32 vs f>=32)
        const float* __restrict__ sp = seq + (size_t)b * T_ * F_ + f;

        float m = 0.0f, v = EPS_, c = 0.0f, xl;

        int t_begin;
        if (ts == 0) {
            xl = sp[0];
            t_begin = 1;                          // t=0 handled in epilogue
        } else {
            const int tw = ts - WARM_;            // >= 24 always
            xl = sp[(size_t)(tw - 1) * F_];
            #pragma unroll 4
            for (int t = tw; t < ts; ++t) {
                float xt = sp[(size_t)t * F_];
                ewa_step(m, v, c, xt, xl);
                xl = xt;
            }
            t_begin = ts;
        }

        #pragma unroll 4
        for (int t = t_begin; t < ts + SUB_; ++t) {
            float xt = sp[(size_t)t * F_];
            ewa_step(m, v, c, xt, xl);
            xl = xt;
            float ac  = c * rsqrtf(fmaf(v, v, EPS_));
            float irr = 1.0f - fabsf(ac);
            #pragma unroll
            for (int o = 16; o; o >>= 1)
                irr += __shfl_xor_sync(0xffffffffu, irr, o);
            if (lane == 0) irrP[wsel][t - t0] = irr;
        }
    };

    // ---- Staggered execution: half the warps run phases in reverse order ----
    if (wid < 4) { do_rowsum(); do_scan(); }
    else         { do_scan();  do_rowsum(); }

    __syncthreads();   // the ONLY mid-kernel barrier

    // ---- Epilogue: pen partial = sum_t irrSum[t] * G[t] (1 t per thread) ----
    float is = irrP[0][tid] + irrP[1][tid];
    if (chunk == 0 && tid == 0) is = (float)F_;   // t=0: ac=0 -> irr=1 per f
    float pen = is * Gs[tid];

    #pragma unroll
    for (int o = 16; o; o >>= 1) {
        ms  += __shfl_xor_sync(0xffffffffu, ms, o);
        pen += __shfl_xor_sync(0xffffffffu, pen, o);
    }
    if (lane == 0) { redM[wid] = ms; redA[wid] = pen; }
    __syncthreads();
    if (tid == 0) {
        float M = 0.0f, A = 0.0f;
        #pragma unroll
        for (int i = 0; i < TPB_ / 32; ++i) { M += redM[i]; A += redA[i]; }
        g_msePart[blockIdx.x] = M;
        g_penPart[blockIdx.x] = A;
        __threadfence();
        s_ticket = atomicAdd(&g_ticket, 1);
    }
    __syncthreads();

    // ---- Last block: deterministic double-precision finalize ----
    if (s_ticket == GRID_ - 1) {
        double pend = 0.0, msed = 0.0;
        for (int i = tid; i < GRID_; i += TPB_) {
            pend += (double)g_penPart[i];
            msed += (double)g_msePart[i];
        }
        #pragma unroll
        for (int o = 16; o; o >>= 1) {
            pend += __shfl_xor_sync(0xffffffffu, pend, o);
            msed += __shfl_xor_sync(0xffffffffu, msed, o);
        }
        if (lane == 0) { dP[wid] = pend; dM[wid] = msed; }
        __syncthreads();
        if (tid == 0) {
            double P = 0.0, M = 0.0;
            #pragma unroll
            for (int i = 0; i < TPB_ / 32; ++i) { P += dP[i]; M += dM[i]; }
            double penalty = P / ((double)B_ * T_ * F_ * H_);
            double msev    = M / ((double)B_ * T_);
            out[0] = (float)(msev + (double)ALPHA_ * penalty);
            g_ticket = 0;                 // reset for next graph replay
        }
    }
}

// ---------------------------------------------------------------------------
extern "C" void kernel_launch(void* const* d_in, const int* in_sizes, int n_in,
                              void* d_out, int out_size)
{
    const float* inp = (const float*)d_in[0];   // input    (B,T,1)
    const float* tgt = (const float*)d_in[1];   // target   (B,T,1)
    const float* seq = (const float*)d_in[2];   // sequence (B,T,F)
    const float* fg  = (const float*)d_in[3];   // forget_gates (B,T,H)
    float* out = (float*)d_out;

    kFused<<<GRID_, TPB_>>>(fg, seq, inp, tgt, out);
}

// round 15
// speedup vs baseline: 2.6202x; 1.2949x over previous
#include <cuda_runtime.h>
#include <cuda_bf16.h>
#include <cstddef>

// Problem constants (fixed shapes from reference)
#define B_   64
#define T_   4096
#define F_   64
#define H_   256
#define EPS_ 1e-8f
#define ALPHA_ 0.5f

// Block owns 256 t. Scan split into 4 sub-chunks of 64 t (one per warp-pair),
// each with a 32-step warm-up (0.5^32 ~ 2.3e-10: far inside fp32 tolerance).
#define CHUNK_  256
#define NCHUNK_ (T_ / CHUNK_)       // 16
#define SUB_    64
#define WARM_   32

#define GRID_   (B_ * NCHUNK_)      // 1024
#define TPB_    256

// Scratch (device globals: no allocation allowed)
__device__ float g_penPart[GRID_];
__device__ float g_msePart[GRID_];
__device__ int   g_ticket;          // zero-initialized; reset by last block

__device__ __forceinline__ void ewa_step(float& m, float& v, float& c,
                                         float xt, float xl)
{
    m = fmaf(0.5f, xt - m, m);          // m = 0.5 m + 0.5 xt
    float r = xt - m;
    v = fmaf(0.5f, fmaf(r, r, -v), v);  // v = 0.5 v + 0.5 r^2
    float q = xl - m;
    c = fmaf(0.5f, fmaf(r, q, -c), c);  // c = 0.5 c + 0.5 r q
}

// ---------------------------------------------------------------------------
// Fused kernel, warp-level phase staggering, NO inter-phase barrier:
//   warps 0-3: rowsum(32 fg rows each -> Gs)  then  scan(own sub-chunk -> irrP)
//   warps 4-7: scan  then  rowsum
// Scan stores 8 partially-reduced irr sums per warp per t (2-shfl butterfly).
// Single __syncthreads() precedes the dot-product epilogue:
//   pen = sum_t (sum_{bank,k} irrP[bank][t][k]) * Gs[t]
// ---------------------------------------------------------------------------
__global__ void __launch_bounds__(TPB_) kFused(
    const float* __restrict__ fg,
    const float* __restrict__ seq,
    const float* __restrict__ inp,
    const float* __restrict__ tgt,
    float* __restrict__ out)
{
    __shared__ float  Gs[CHUNK_];
    __shared__ float  irrP[2][CHUNK_][9];   // 9: pad, 9 coprime 32 -> no conflicts
    __shared__ float  redA[TPB_ / 32];
    __shared__ float  redM[TPB_ / 32];
    __shared__ int    s_ticket;
    __shared__ double dP[TPB_ / 32], dM[TPB_ / 32];

    const int tid  = threadIdx.x;
    const int wid  = tid >> 5;
    const int lane = tid & 31;
    const int b     = blockIdx.x >> 4;            // / NCHUNK_
    const int chunk = blockIdx.x & (NCHUNK_ - 1);
    const int t0    = chunk * CHUNK_;

    const float4* __restrict__ fg4 = (const float4*)fg;

    // ---- MSE: exactly one element per thread (B*T == GRID_*TPB_) ----
    float ms;
    {
        const int i = blockIdx.x * TPB_ + tid;
        float d = inp[i] - tgt[i];
        ms = d * d;
    }

    // ---- Phase work definitions ----
    auto do_rowsum = [&]() {
        const size_t rowbase = (size_t)(b * T_ + t0) * (H_ / 4);
        #pragma unroll 2
        for (int r = wid * 2; r < CHUNK_; r += 16) {
            size_t b0 = rowbase + (size_t)r * (H_ / 4);
            size_t b1 = b0 + (H_ / 4);
            float4 a0 = __ldcs(&fg4[b0 + lane]);       // streaming: touched once
            float4 a1 = __ldcs(&fg4[b0 + 32 + lane]);
            float4 c0 = __ldcs(&fg4[b1 + lane]);
            float4 c1 = __ldcs(&fg4[b1 + 32 + lane]);
            float s0 = (a0.x + a0.y) + (a0.z + a0.w) + (a1.x + a1.y) + (a1.z + a1.w);
            float s1 = (c0.x + c0.y) + (c0.z + c0.w) + (c1.x + c1.y) + (c1.z + c1.w);
            #pragma unroll
            for (int o = 16; o; o >>= 1) {
                s0 += __shfl_xor_sync(0xffffffffu, s0, o);
                s1 += __shfl_xor_sync(0xffffffffu, s1, o);
            }
            if (lane == 0) { Gs[r] = s0; Gs[r + 1] = s1; }
        }
    };

    auto do_scan = [&]() {
        const int f  = tid & (F_ - 1);
        const int g  = tid >> 6;                  // sub-chunk 0..3
        const int ts = t0 + g * SUB_;             // sub-chunk start
        const int wsel = wid & 1;                 // irrP bank (f<32 vs f>=32)
        const float* __restrict__ sp = seq + (size_t)b * T_ * F_ + f;

        float m = 0.0f, v = EPS_, c = 0.0f, xl;

        int t_begin;
        if (ts == 0) {
            xl = sp[0];
            t_begin = 1;                          // t=0 handled in epilogue
        } else {
            const int tw = ts - WARM_;            // >= 32 always
            xl = sp[(size_t)(tw - 1) * F_];
            #pragma unroll 4
            for (int t = tw; t < ts; ++t) {
                float xt = sp[(size_t)t * F_];
                ewa_step(m, v, c, xt, xl);
                xl = xt;
            }
            t_begin = ts;
        }

        #pragma unroll 4
        for (int t = t_begin; t < ts + SUB_; ++t) {
            float xt = sp[(size_t)t * F_];
            ewa_step(m, v, c, xt, xl);
            xl = xt;
            float ac  = c * rsqrtf(fmaf(v, v, EPS_));
            float irr = 1.0f - fabsf(ac);
            // 2-shfl butterfly: lanes 0-7 end with the 8 group sums
            irr += __shfl_xor_sync(0xffffffffu, irr, 16);
            irr += __shfl_xor_sync(0xffffffffu, irr, 8);
            if (lane < 8) irrP[wsel][t - t0][lane] = irr;
        }
    };

    // ---- Staggered execution: half the warps run phases in reverse order ----
    if (wid < 4) { do_rowsum(); do_scan(); }
    else         { do_scan();  do_rowsum(); }

    __syncthreads();   // the ONLY mid-kernel barrier

    // ---- Epilogue: pen partial = sum_t irrSum[t] * G[t] (1 t per thread) ----
    float is = 0.0f;
    #pragma unroll
    for (int k = 0; k < 8; ++k)
        is += irrP[0][tid][k] + irrP[1][tid][k];
    if (chunk == 0 && tid == 0) is = (float)F_;   // t=0: ac=0 -> irr=1 per f
    float pen = is * Gs[tid];

    #pragma unroll
    for (int o = 16; o; o >>= 1) {
        ms  += __shfl_xor_sync(0xffffffffu, ms, o);
        pen += __shfl_xor_sync(0xffffffffu, pen, o);
    }
    if (lane == 0) { redM[wid] = ms; redA[wid] = pen; }
    __syncthreads();
    if (tid == 0) {
        float M = 0.0f, A = 0.0f;
        #pragma unroll
        for (int i = 0; i < TPB_ / 32; ++i) { M += redM[i]; A += redA[i]; }
        g_msePart[blockIdx.x] = M;
        g_penPart[blockIdx.x] = A;
        __threadfence();
        s_ticket = atomicAdd(&g_ticket, 1);
    }
    __syncthreads();

    // ---- Last block: deterministic double-precision finalize ----
    if (s_ticket == GRID_ - 1) {
        double pend = 0.0, msed = 0.0;
        for (int i = tid; i < GRID_; i += TPB_) {
            pend += (double)g_penPart[i];
            msed += (double)g_msePart[i];
        }
        #pragma unroll
        for (int o = 16; o; o >>= 1) {
            pend += __shfl_xor_sync(0xffffffffu, pend, o);
            msed += __shfl_xor_sync(0xffffffffu, msed, o);
        }
        if (lane == 0) { dP[wid] = pend; dM[wid] = msed; }
        __syncthreads();
        if (tid == 0) {
            double P = 0.0, M = 0.0;
            #pragma unroll
            for (int i = 0; i < TPB_ / 32; ++i) { P += dP[i]; M += dM[i]; }
            double penalty = P / ((double)B_ * T_ * F_ * H_);
            double msev    = M / ((double)B_ * T_);
            out[0] = (float)(msev + (double)ALPHA_ * penalty);
            g_ticket = 0;                 // reset for next graph replay
        }
    }
}

// ---------------------------------------------------------------------------
extern "C" void kernel_launch(void* const* d_in, const int* in_sizes, int n_in,
                              void* d_out, int out_size)
{
    const float* inp = (const float*)d_in[0];   // input    (B,T,1)
    const float* tgt = (const float*)d_in[1];   // target   (B,T,1)
    const float* seq = (const float*)d_in[2];   // sequence (B,T,F)
    const float* fg  = (const float*)d_in[3];   // forget_gates (B,T,H)
    float* out = (float*)d_out;

    kFused<<<GRID_, TPB_>>>(fg, seq, inp, tgt, out);
}